// round 6
// baseline (speedup 1.0000x reference)
#include <cuda_runtime.h>
#include <cstdint>

// CRF forward log-partition. B=512, T=1024, L=64.
// One warp per batch. Lane l owns output rows (2l, 2l+1).
// p lives in ONE register pair per lane; the all-to-all broadcast each step
// uses SHFL.IDX (no shared memory, no barriers on the critical path).
//   p_{t+1} = (E @ p_t) .* exp(logit_t),  E = exp(trans) in 128 registers.
// Exact power-of-2 rescale every 4 steps, deferred: REDUX result folds into
// the NEXT step's exp(logit) (needed ~130cyc later -> fully hidden).
// logZ = ktot*ln2 + log( pend * sum_j p[j] * exp(trans[63,j]) ).

#define CRF_B 512
#define CRF_T 1024
#define CRF_L 64
#define C_LOG2E 1.4426950408889634f
#define C_LN2   0.6931471805599453f
#define FULLM  0xffffffffu

using u64 = unsigned long long;

__device__ __forceinline__ float ex2f(float x) {
    float r; asm("ex2.approx.f32 %0, %1;" : "=f"(r) : "f"(x)); return r;
}
__device__ __forceinline__ u64 packf2(float lo, float hi) {
    u64 r; asm("mov.b64 %0, {%1, %2};" : "=l"(r) : "f"(lo), "f"(hi)); return r;
}
__device__ __forceinline__ void unpackf2(u64 v, float& lo, float& hi) {
    asm("mov.b64 {%0, %1}, %2;" : "=f"(lo), "=f"(hi) : "l"(v));
}
#define FMA2(acc, a, b) \
    asm("fma.rn.f32x2 %0, %1, %2, %0;" : "+l"(acc) : "l"(a), "l"(b))
#define ADD2(acc, a) \
    asm("add.rn.f32x2 %0, %0, %1;" : "+l"(acc) : "l"(a))

__device__ __forceinline__ float2 eexp(float2 lg) {
    return make_float2(ex2f(lg.x * C_LOG2E), ex2f(lg.y * C_LOG2E));
}

// One CRF step entirely in registers. pp = this lane's (p[2l], p[2l+1]).
// el = prefetched exp(logit) pair. pend = deferred 2^-k from the previous
// rescale step (1.0 otherwise); consumed here, off the critical path.
template <bool RESCALE>
__device__ __forceinline__ u64 crf_step(
    float2 el, u64 pp,
    const u64 (&Ea)[32], const u64 (&Eb)[32],
    int& ktot, float& pend)
{
    el.x *= pend;
    el.y *= pend;

    u64 a0 = 0ull, a1 = 0ull, a2 = 0ull, a3 = 0ull;
    u64 b0 = 0ull, b1 = 0ull, b2 = 0ull, b3 = 0ull;
#pragma unroll
    for (int j = 0; j < 32; j += 4) {       // SHFL broadcast of p pairs
        u64 q0 = __shfl_sync(FULLM, pp, j);
        u64 q1 = __shfl_sync(FULLM, pp, j + 1);
        u64 q2 = __shfl_sync(FULLM, pp, j + 2);
        u64 q3 = __shfl_sync(FULLM, pp, j + 3);
        FMA2(a0, Ea[j],     q0);
        FMA2(b0, Eb[j],     q0);
        FMA2(a1, Ea[j + 1], q1);
        FMA2(b1, Eb[j + 1], q1);
        FMA2(a2, Ea[j + 2], q2);
        FMA2(b2, Eb[j + 2], q2);
        FMA2(a3, Ea[j + 3], q3);
        FMA2(b3, Eb[j + 3], q3);
    }
    ADD2(a0, a1); ADD2(a2, a3); ADD2(a0, a2);
    ADD2(b0, b1); ADD2(b2, b3); ADD2(b0, b2);
    float ax, ay, bx, by;
    unpackf2(a0, ax, ay);
    unpackf2(b0, bx, by);
    float px = (ax + ay) * el.x;            // new p[2l]
    float py = (bx + by) * el.y;            // new p[2l+1]
    u64 ppn = packf2(px, py);

    if (RESCALE) {
        // Result only needed at the END of the next step -> hidden.
        unsigned mu = __reduce_max_sync(FULLM,
                          __float_as_uint(fmaxf(px, py)));
        int k = (int)(mu >> 23) - 127;
        ktot += k;
        pend = __int_as_float((127 - k) << 23);   // exact 2^-k
    } else {
        pend = 1.0f;
    }
    return ppn;
}

__global__ void __launch_bounds__(128)
crf_fwd_kernel(const float* __restrict__ logits,
               const int*   __restrict__ lens,
               const float* __restrict__ trans,
               float*       __restrict__ out)
{
    const int w    = threadIdx.x >> 5;
    const int lane = threadIdx.x & 31;
    const int b    = blockIdx.x * 4 + w;    // grid=128 -> b < 512

    // ---- E = exp(trans), rows 2*lane and 2*lane+1, packed f32x2 ----
    u64 Ea[32], Eb[32];
    const float* ra = trans + (2 * lane)     * CRF_L;
    const float* rb = trans + (2 * lane + 1) * CRF_L;
#pragma unroll
    for (int jj = 0; jj < 32; jj++) {
        Ea[jj] = packf2(expf(ra[2 * jj]), expf(ra[2 * jj + 1]));
        Eb[jj] = packf2(expf(rb[2 * jj]), expf(rb[2 * jj + 1]));
    }
    const float2 e63 = make_float2(expf(trans[63 * CRF_L + 2 * lane]),
                                   expf(trans[63 * CRF_L + 2 * lane + 1]));

    // ---- init: delta at start label 62 (lane 31 holds rows 62,63) ----
    u64 pp = packf2((2 * lane == 62) ? 1.0f : 0.0f,
                    (2 * lane + 1 == 62) ? 1.0f : 0.0f);

    int   ktot = 0;
    float pend = 1.0f;
    const int len = lens[b];

    const float2* lgp =
        reinterpret_cast<const float2*>(logits + (size_t)b * CRF_T * CRF_L) + lane;

    // 4-deep prefetch; exp(logit) computed off the critical path.
    float2 e0, e1, e2, e3;
    if (len > 0) e0 = eexp(__ldg(lgp));
    if (len > 1) e1 = eexp(__ldg(lgp + 32));
    if (len > 2) e2 = eexp(__ldg(lgp + 64));
    if (len > 3) e3 = eexp(__ldg(lgp + 96));

    int t = 0;
    for (; t + 4 <= len; t += 4) {
        float2 g;
        g = e0; if (t + 4 < len) e0 = eexp(__ldg(lgp + (size_t)(t + 4) * 32));
        pp = crf_step<false>(g, pp, Ea, Eb, ktot, pend);
        g = e1; if (t + 5 < len) e1 = eexp(__ldg(lgp + (size_t)(t + 5) * 32));
        pp = crf_step<false>(g, pp, Ea, Eb, ktot, pend);
        g = e2; if (t + 6 < len) e2 = eexp(__ldg(lgp + (size_t)(t + 6) * 32));
        pp = crf_step<false>(g, pp, Ea, Eb, ktot, pend);
        g = e3; if (t + 7 < len) e3 = eexp(__ldg(lgp + (size_t)(t + 7) * 32));
        pp = crf_step<true >(g, pp, Ea, Eb, ktot, pend);
    }

    // remainder (<=3 steps); e0..e2 already hold the right prefetches.
    if (t < len) { pp = crf_step<false>(e0, pp, Ea, Eb, ktot, pend); t++; }
    if (t < len) { pp = crf_step<false>(e1, pp, Ea, Eb, ktot, pend); t++; }
    if (t < len) { pp = crf_step<false>(e2, pp, Ea, Eb, ktot, pend); t++; }

    // ---- finalize: logZ = ktot*ln2 + log( pend * sum_j p[j]*E[63,j] ) ----
    float px, py;
    unpackf2(pp, px, py);
    float part = e63.x * px + e63.y * py;
#pragma unroll
    for (int o = 16; o > 0; o >>= 1)
        part += __shfl_xor_sync(FULLM, part, o);
    if (lane == 0)
        out[b] = (float)ktot * C_LN2 + __logf(part * pend);
}

extern "C" void kernel_launch(void* const* d_in, const int* in_sizes, int n_in,
                              void* d_out, int out_size)
{
    const float* logits = (const float*)d_in[0];   // [512,1024,64] f32
    const int*   lens   = (const int*)  d_in[1];   // [512] i32
    const float* trans  = (const float*)d_in[2];   // [64,64] f32
    float* out = (float*)d_out;                    // [512] f32

    crf_fwd_kernel<<<CRF_B / 4, 128>>>(logits, lens, trans, out);
}

// round 7
// speedup vs baseline: 1.1493x; 1.1493x over previous
#include <cuda_runtime.h>
#include <cstdint>

// CRF forward log-partition. B=512, T=1024, L=64.
// One warp per batch; lane l owns output rows (2l, 2l+1).
// Probability-domain recurrence: p_{t+1} = (E @ p_t) .* exp(logit_t),
// E = exp(trans) in 128 registers. Inner loop is the R1 schedule verbatim
// (paired LDS.64 broadcasts + named scalar accumulators) -- the only shape
// ptxas front-batches. Changes vs R1: rescale every 4th step only, issued
// AFTER the store, folded into the NEXT step's exp(logit) (consumed ~150cyc
// later -> off the critical path); eexp no longer depends on kf.
// logZ = ktot*ln2 + log( pend * sum_j p[j] * exp(trans[63,j]) ).

#define CRF_B 512
#define CRF_T 1024
#define CRF_L 64
#define C_LOG2E 1.4426950408889634f
#define C_LN2   0.6931471805599453f
#define FULLM  0xffffffffu

using u64 = unsigned long long;

__device__ __forceinline__ float ex2f(float x) {
    float r; asm("ex2.approx.f32 %0, %1;" : "=f"(r) : "f"(x)); return r;
}
__device__ __forceinline__ u64 packf2(float lo, float hi) {
    u64 r; asm("mov.b64 %0, {%1, %2};" : "=l"(r) : "f"(lo), "f"(hi)); return r;
}
__device__ __forceinline__ void unpackf2(u64 v, float& lo, float& hi) {
    asm("mov.b64 {%0, %1}, %2;" : "=f"(lo), "=f"(hi) : "l"(v));
}
#define FMA2(acc, a, b) \
    asm("fma.rn.f32x2 %0, %1, %2, %0;" : "+l"(acc) : "l"(a), "l"(b))
#define ADD2(acc, a) \
    asm("add.rn.f32x2 %0, %0, %1;" : "+l"(acc) : "l"(a))

__device__ __forceinline__ float2 eexp(float2 lg) {
    return make_float2(ex2f(lg.x * C_LOG2E), ex2f(lg.y * C_LOG2E));
}

// One CRF step; R1 inner loop verbatim. Reads p from sp_r (32x LDS.64
// broadcast), writes this lane's new pair to sp_w.
// pend: deferred exact 2^-k from the previous rescale step (1.0 otherwise),
// applied to el at entry (operands ready -> off the critical path).
template <bool RESCALE>
__device__ __forceinline__ void crf_step(
    float2 el,
    const u64 (&Ea)[32], const u64 (&Eb)[32],
    const float2* __restrict__ sp_r,
    u64* __restrict__ sp_w,
    int lane, int& ktot, float& pend)
{
    float elA = el.x * pend;
    float elB = el.y * pend;

    u64 a0 = 0ull, a1 = 0ull, b0 = 0ull, b1 = 0ull;
#pragma unroll
    for (int jj = 0; jj < 32; jj += 2) {
        u64 p0 = *reinterpret_cast<const u64*>(sp_r + jj);
        u64 p1 = *reinterpret_cast<const u64*>(sp_r + jj + 1);
        FMA2(a0, Ea[jj],     p0);
        FMA2(b0, Eb[jj],     p0);
        FMA2(a1, Ea[jj + 1], p1);
        FMA2(b1, Eb[jj + 1], p1);
    }
    ADD2(a0, a1);
    ADD2(b0, b1);
    float ax, ay, bx, by;
    unpackf2(a0, ax, ay);
    unpackf2(b0, bx, by);
    float pA = (ax + ay) * elA;            // new p[2*lane]
    float pB = (bx + by) * elB;            // new p[2*lane+1]

    sp_w[lane] = packf2(pA, pB);           // store FIRST (unrescaled)

    if (RESCALE) {
        // After the store; pend is consumed ~150cyc into the next step.
        float m = fmaxf(pA, pB);           // p > 0: uint cmp == float cmp
        unsigned mu = __reduce_max_sync(FULLM, __float_as_uint(m));
        int k = (int)(mu >> 23) - 127;
        ktot += k;
        pend = __int_as_float((127 - k) << 23);   // exact 2^-k
    } else {
        pend = 1.0f;
    }

    __syncwarp();
}

__global__ void __launch_bounds__(128)
crf_fwd_kernel(const float* __restrict__ logits,
               const int*   __restrict__ lens,
               const float* __restrict__ trans,
               float*       __restrict__ out)
{
    __shared__ __align__(16) float2 sp[4][2][32];   // [warp][buffer][pair]

    const int w    = threadIdx.x >> 5;
    const int lane = threadIdx.x & 31;
    const int b    = blockIdx.x * 4 + w;            // grid=128 -> b < 512

    const float2* rd0 = sp[w][0];
    const float2* rd1 = sp[w][1];
    u64* wr0 = reinterpret_cast<u64*>(sp[w][0]);
    u64* wr1 = reinterpret_cast<u64*>(sp[w][1]);

    // ---- E = exp(trans), rows 2*lane and 2*lane+1, packed f32x2 ----
    u64 Ea[32], Eb[32];
    const float* ra = trans + (2 * lane)     * CRF_L;
    const float* rb = trans + (2 * lane + 1) * CRF_L;
#pragma unroll
    for (int jj = 0; jj < 32; jj++) {
        Ea[jj] = packf2(expf(ra[2 * jj]), expf(ra[2 * jj + 1]));
        Eb[jj] = packf2(expf(rb[2 * jj]), expf(rb[2 * jj + 1]));
    }
    const float2 e63 = make_float2(expf(trans[63 * CRF_L + 2 * lane]),
                                   expf(trans[63 * CRF_L + 2 * lane + 1]));

    // ---- init: delta at start label 62 ----
    wr0[lane] = packf2((2 * lane == 62) ? 1.0f : 0.0f,
                       (2 * lane + 1 == 62) ? 1.0f : 0.0f);
    __syncwarp();

    int   ktot = 0;
    float pend = 1.0f;
    const int len = lens[b];

    const float2* lgp =
        reinterpret_cast<const float2*>(logits + (size_t)b * CRF_T * CRF_L) + lane;

    // 4-deep prefetch of exp(logit) pairs (no kf dependence -> off path).
    float2 e0, e1, e2, e3;
    if (len > 0) e0 = eexp(__ldg(lgp));
    if (len > 1) e1 = eexp(__ldg(lgp + 32));
    if (len > 2) e2 = eexp(__ldg(lgp + 64));
    if (len > 3) e3 = eexp(__ldg(lgp + 96));

    int t = 0;
    for (; t + 4 <= len; t += 4) {       // p in buffer 0 at loop top
        float2 g;
        g = e0; if (t + 4 < len) e0 = eexp(__ldg(lgp + (size_t)(t + 4) * 32));
        crf_step<false>(g, Ea, Eb, rd0, wr1, lane, ktot, pend);
        g = e1; if (t + 5 < len) e1 = eexp(__ldg(lgp + (size_t)(t + 5) * 32));
        crf_step<false>(g, Ea, Eb, rd1, wr0, lane, ktot, pend);
        g = e2; if (t + 6 < len) e2 = eexp(__ldg(lgp + (size_t)(t + 6) * 32));
        crf_step<false>(g, Ea, Eb, rd0, wr1, lane, ktot, pend);
        g = e3; if (t + 7 < len) e3 = eexp(__ldg(lgp + (size_t)(t + 7) * 32));
        crf_step<true >(g, Ea, Eb, rd1, wr0, lane, ktot, pend);
    }

    // remainder (<=3 steps); e0..e2 already hold the right values.
    int buf = 0;
    if (t < len) { crf_step<false>(e0, Ea, Eb, rd0, wr1, lane, ktot, pend); t++; buf = 1; }
    if (t < len) { crf_step<false>(e1, Ea, Eb, rd1, wr0, lane, ktot, pend); t++; buf = 0; }
    if (t < len) { crf_step<false>(e2, Ea, Eb, rd0, wr1, lane, ktot, pend); t++; buf = 1; }

    // ---- finalize: logZ = ktot*ln2 + log( pend * sum_j p[j]*E[63,j] ) ----
    float px, py;
    unpackf2((len & 3) ? (buf ? wr1 : wr0)[lane] : wr0[lane], px, py);
    float part = e63.x * px + e63.y * py;
#pragma unroll
    for (int o = 16; o > 0; o >>= 1)
        part += __shfl_xor_sync(FULLM, part, o);
    if (lane == 0)
        out[b] = (float)ktot * C_LN2 + __logf(part * pend);
}

extern "C" void kernel_launch(void* const* d_in, const int* in_sizes, int n_in,
                              void* d_out, int out_size)
{
    const float* logits = (const float*)d_in[0];   // [512,1024,64] f32
    const int*   lens   = (const int*)  d_in[1];   // [512] i32
    const float* trans  = (const float*)d_in[2];   // [64,64] f32
    float* out = (float*)d_out;                    // [512] f32

    crf_fwd_kernel<<<CRF_B / 4, 128>>>(logits, lens, trans, out);
}

// round 8
// speedup vs baseline: 1.1599x; 1.0092x over previous
#include <cuda_runtime.h>
#include <cstdint>

// CRF forward log-partition. B=512, T=1024, L=64.
// One warp per batch; lane l owns output rows (2l, 2l+1).
// Probability-domain recurrence: p_{t+1} = (E @ p_t) .* exp(logit_t),
// E = exp(trans) in 128 registers.
//
// Structure is R1's proven schedule byte-for-byte where it matters:
//  - RAW logit prefetch q0..q3 (consumed 4 iterations later -> DRAM latency
//    never stalls issue; eexp-in-prefetch was the 3x regression in R2-R7).
//  - paired LDS.64 broadcasts + named scalar accumulators.
//  - ex2 inside the step, after the FMA tree (R1 position), but with NO
//    dependence on the rescale state.
// Rescale: split across steps so nothing waits. Step t%4==3 issues
// REDUX.MAX -> mu with no consumer (no stall); step t%4==0 of the next group
// converts mu -> exact 2^-k and folds it into exp(logit) (consumed ~160cyc
// later). ktot is an exact integer; logZ = ktot*ln2 + log(sum p[j]*E63[j]).

#define CRF_B 512
#define CRF_T 1024
#define CRF_L 64
#define C_LOG2E 1.4426950408889634f
#define C_LN2   0.6931471805599453f
#define FULLM  0xffffffffu

using u64 = unsigned long long;

__device__ __forceinline__ float ex2f(float x) {
    float r; asm("ex2.approx.f32 %0, %1;" : "=f"(r) : "f"(x)); return r;
}
__device__ __forceinline__ u64 packf2(float lo, float hi) {
    u64 r; asm("mov.b64 %0, {%1, %2};" : "=l"(r) : "f"(lo), "f"(hi)); return r;
}
__device__ __forceinline__ void unpackf2(u64 v, float& lo, float& hi) {
    asm("mov.b64 {%0, %1}, %2;" : "=f"(lo), "=f"(hi) : "l"(v));
}
#define FMA2(acc, a, b) \
    asm("fma.rn.f32x2 %0, %1, %2, %0;" : "+l"(acc) : "l"(a), "l"(b))
#define ADD2(acc, a) \
    asm("add.rn.f32x2 %0, %0, %1;" : "+l"(acc) : "l"(a))

// One CRF step. lg = RAW logit pair (prefetched 4 steps ago).
// FOLD: convert mu (REDUX result from previous group's last step; long since
//       complete) into exact 2^-k, add k to ktot, fold into el.
// RESCALE: issue REDUX.MAX into mu AFTER the store; no consumer this step.
template <bool FOLD, bool RESCALE>
__device__ __forceinline__ void crf_step(
    float2 lg,
    const u64 (&Ea)[32], const u64 (&Eb)[32],
    const float2* __restrict__ sp_r,
    u64* __restrict__ sp_w,
    int lane, int& ktot, unsigned& mu)
{
    float s = 1.0f;
    if (FOLD) {
        int k = (int)(mu >> 23) - 127;
        ktot += k;
        s = __int_as_float((127 - k) << 23);     // exact 2^-k
    }

    u64 a0 = 0ull, a1 = 0ull, b0 = 0ull, b1 = 0ull;
#pragma unroll
    for (int jj = 0; jj < 32; jj += 2) {
        u64 p0 = *reinterpret_cast<const u64*>(sp_r + jj);
        u64 p1 = *reinterpret_cast<const u64*>(sp_r + jj + 1);
        FMA2(a0, Ea[jj],     p0);
        FMA2(b0, Eb[jj],     p0);
        FMA2(a1, Ea[jj + 1], p1);
        FMA2(b1, Eb[jj + 1], p1);
    }
    ADD2(a0, a1);
    ADD2(b0, b1);
    float ax, ay, bx, by;
    unpackf2(a0, ax, ay);
    unpackf2(b0, bx, by);
    float sA = ax + ay;
    float sB = bx + by;

    float elA = ex2f(lg.x * C_LOG2E);            // R1 position for the MUFUs
    float elB = ex2f(lg.y * C_LOG2E);
    if (FOLD) { elA *= s; elB *= s; }

    float pA = sA * elA;                         // new p[2*lane]
    float pB = sB * elB;                         // new p[2*lane+1]

    sp_w[lane] = packf2(pA, pB);                 // store (unrescaled)

    if (RESCALE) {
        // No consumer of mu in this step -> no scoreboard stall here.
        mu = __reduce_max_sync(FULLM, __float_as_uint(fmaxf(pA, pB)));
    }
    __syncwarp();
}

__global__ void __launch_bounds__(128)
crf_fwd_kernel(const float* __restrict__ logits,
               const int*   __restrict__ lens,
               const float* __restrict__ trans,
               float*       __restrict__ out)
{
    __shared__ __align__(16) float2 sp[4][2][32];   // [warp][buffer][pair]

    const int w    = threadIdx.x >> 5;
    const int lane = threadIdx.x & 31;
    const int b    = blockIdx.x * 4 + w;            // grid=128 -> b < 512

    const float2* rd0 = sp[w][0];
    const float2* rd1 = sp[w][1];
    u64* wr0 = reinterpret_cast<u64*>(sp[w][0]);
    u64* wr1 = reinterpret_cast<u64*>(sp[w][1]);

    // ---- E = exp(trans), rows 2*lane and 2*lane+1, packed f32x2 ----
    u64 Ea[32], Eb[32];
    const float* ra = trans + (2 * lane)     * CRF_L;
    const float* rb = trans + (2 * lane + 1) * CRF_L;
#pragma unroll
    for (int jj = 0; jj < 32; jj++) {
        Ea[jj] = packf2(expf(ra[2 * jj]), expf(ra[2 * jj + 1]));
        Eb[jj] = packf2(expf(rb[2 * jj]), expf(rb[2 * jj + 1]));
    }
    const float2 e63 = make_float2(expf(trans[63 * CRF_L + 2 * lane]),
                                   expf(trans[63 * CRF_L + 2 * lane + 1]));

    // ---- init: delta at start label 62 ----
    wr0[lane] = packf2((2 * lane == 62) ? 1.0f : 0.0f,
                       (2 * lane + 1 == 62) ? 1.0f : 0.0f);
    __syncwarp();

    int      ktot = 0;
    unsigned mu   = 0x3f800000u;                 // 1.0f bits -> first fold k=0
    const int len = lens[b];

    const float2* lgp =
        reinterpret_cast<const float2*>(logits + (size_t)b * CRF_T * CRF_L) + lane;

    // 4-deep RAW prefetch (no computation touches these until consumed).
    float2 q0, q1, q2, q3;
    if (len > 0) q0 = __ldg(lgp);
    if (len > 1) q1 = __ldg(lgp + 32);
    if (len > 2) q2 = __ldg(lgp + 64);
    if (len > 3) q3 = __ldg(lgp + 96);

    int t = 0;
    for (; t + 4 <= len; t += 4) {               // p in buffer 0 at loop top
        float2 g;
        g = q0; if (t + 4 < len) q0 = __ldg(lgp + (size_t)(t + 4) * 32);
        crf_step<true,  false>(g, Ea, Eb, rd0, wr1, lane, ktot, mu);
        g = q1; if (t + 5 < len) q1 = __ldg(lgp + (size_t)(t + 5) * 32);
        crf_step<false, false>(g, Ea, Eb, rd1, wr0, lane, ktot, mu);
        g = q2; if (t + 6 < len) q2 = __ldg(lgp + (size_t)(t + 6) * 32);
        crf_step<false, false>(g, Ea, Eb, rd0, wr1, lane, ktot, mu);
        g = q3; if (t + 7 < len) q3 = __ldg(lgp + (size_t)(t + 7) * 32);
        crf_step<false, true >(g, Ea, Eb, rd1, wr0, lane, ktot, mu);
    }

    // remainder (<=3 steps): q0..q2 hold the right raw values.
    // First remainder step folds the last group's pending mu.
    if (t < len) { crf_step<true,  false>(q0, Ea, Eb, rd0, wr1, lane, ktot, mu); t++; }
    if (t < len) { crf_step<false, false>(q1, Ea, Eb, rd1, wr0, lane, ktot, mu); t++; }
    if (t < len) { crf_step<false, false>(q2, Ea, Eb, rd0, wr1, lane, ktot, mu); t++; }

    // ---- finalize: logZ = ktot*ln2 + log( sum_j p[j]*E[63,j] ) ----
    // A trailing un-folded mu is ignored: ktot never counted it and p is
    // stored unrescaled, so the invariant alpha = log(p) + ktot*ln2 holds.
    float px, py;
    unpackf2((len & 1) ? wr1[lane] : wr0[lane], px, py);
    float part = e63.x * px + e63.y * py;
#pragma unroll
    for (int o = 16; o > 0; o >>= 1)
        part += __shfl_xor_sync(FULLM, part, o);
    if (lane == 0)
        out[b] = (float)ktot * C_LN2 + __logf(part);
}

extern "C" void kernel_launch(void* const* d_in, const int* in_sizes, int n_in,
                              void* d_out, int out_size)
{
    const float* logits = (const float*)d_in[0];   // [512,1024,64] f32
    const int*   lens   = (const int*)  d_in[1];   // [512] i32
    const float* trans  = (const float*)d_in[2];   // [64,64] f32
    float* out = (float*)d_out;                    // [512] f32

    crf_fwd_kernel<<<CRF_B / 4, 128>>>(logits, lens, trans, out);
}

// round 9
// speedup vs baseline: 2.2623x; 1.9505x over previous
#include <cuda_runtime.h>
#include <cstdint>
#include <cstddef>

// CRF forward log-partition. B=512, T=1024, L=64.
// Fwd/bwd split: Z = e63^T M_{len-1}...M_0 delta,  M_t = diag(el_t) E.
//   warp 0 (fwd): p_m   = M_{m-1}...M_0 delta_start        (m = len/2 steps)
//   warp 1 (bwd): b_m   = M_m^T...M_{len-1}^T e63          (len-m steps)
//                 via v' = el .* (E^T v)  -- SAME step structure, E^T in regs,
//                 logits in reverse; final bare step uses el = exp(0) = 1.
//   logZ = cF + cB + log( sum_j p_m[j] * b_m[j] )
// Each warp runs Round-1's proven step verbatim (prob domain, per-step exact
// power-of-2 rescale via REDUX on float bits; c accumulates applied scales).

#define CRF_B 512
#define CRF_T 1024
#define CRF_L 64
#define C_LOG2E 1.4426950408889634f
#define C_LN2   0.6931471805599453f
#define FULLM  0xffffffffu

using u64 = unsigned long long;

__device__ __forceinline__ float ex2f(float x) {
    float r; asm("ex2.approx.f32 %0, %1;" : "=f"(r) : "f"(x)); return r;
}
__device__ __forceinline__ u64 packf2(float lo, float hi) {
    u64 r; asm("mov.b64 %0, {%1, %2};" : "=l"(r) : "f"(lo), "f"(hi)); return r;
}
__device__ __forceinline__ void unpackf2(u64 v, float& lo, float& hi) {
    asm("mov.b64 {%0, %1}, %2;" : "=f"(lo), "=f"(hi) : "l"(v));
}
#define FMA2(acc, a, b) \
    asm("fma.rn.f32x2 %0, %1, %2, %0;" : "+l"(acc) : "l"(a), "l"(b))
#define ADD2(acc, a) \
    asm("add.rn.f32x2 %0, %0, %1;" : "+l"(acc) : "l"(a))

// ---- Round-1 crf_step, verbatim ----
__device__ __forceinline__ void crf_step(
    float2 lg,
    const u64 (&Ea)[32], const u64 (&Eb)[32],
    const float2* __restrict__ sp_r,
    u64* __restrict__ sp_w,
    int lane, float& c, float& kf)
{
    u64 a0 = 0ull, a1 = 0ull, b0 = 0ull, b1 = 0ull;
#pragma unroll
    for (int jj = 0; jj < 32; jj += 2) {
        u64 p0 = *reinterpret_cast<const u64*>(sp_r + jj);
        u64 p1 = *reinterpret_cast<const u64*>(sp_r + jj + 1);
        FMA2(a0, Ea[jj],     p0);
        FMA2(b0, Eb[jj],     p0);
        FMA2(a1, Ea[jj + 1], p1);
        FMA2(b1, Eb[jj + 1], p1);
    }
    ADD2(a0, a1);
    ADD2(b0, b1);
    float ax, ay, bx, by;
    unpackf2(a0, ax, ay);
    unpackf2(b0, bx, by);
    float sA = ax + ay;
    float sB = bx + by;

    float elA = ex2f(fmaf(lg.x, C_LOG2E, -kf));
    float elB = ex2f(fmaf(lg.y, C_LOG2E, -kf));
    float pA = sA * elA;
    float pB = sB * elB;

    sp_w[lane] = packf2(pA, pB);

    c = fmaf(kf, C_LN2, c);
    float m = fmaxf(pA, pB);
    unsigned mu = __reduce_max_sync(FULLM, __float_as_uint(m));
    kf = (float)((int)(mu >> 23) - 127);

    __syncwarp();
}

// Round-1 main loop, verbatim, parameterized by compile-time stride sign.
// Runs nlog logit steps starting at lgp and stepping SGN*32 float2s, then an
// optional bare step (lg = 0 -> el = 2^-kf, applies pending rescale).
template <int SGN>
__device__ __forceinline__ float run_chain(
    const float2* __restrict__ lgp, int nlog, bool bare,
    const u64 (&Ea)[32], const u64 (&Eb)[32],
    const float2* rd0, const float2* rd1,
    u64* wr0, u64* wr1, int lane)
{
    float c = 0.0f, kf = 0.0f;

    float2 q0, q1, q2, q3;
    if (nlog > 0) q0 = __ldg(lgp);
    if (nlog > 1) q1 = __ldg(lgp + SGN * 32);
    if (nlog > 2) q2 = __ldg(lgp + SGN * 64);
    if (nlog > 3) q3 = __ldg(lgp + SGN * 96);

    int t = 0;
    for (; t + 4 <= nlog; t += 4) {
        float2 g;
        g = q0; if (t + 4 < nlog) q0 = __ldg(lgp + (ptrdiff_t)SGN * (t + 4) * 32);
        crf_step(g, Ea, Eb, rd0, wr1, lane, c, kf);
        g = q1; if (t + 5 < nlog) q1 = __ldg(lgp + (ptrdiff_t)SGN * (t + 5) * 32);
        crf_step(g, Ea, Eb, rd1, wr0, lane, c, kf);
        g = q2; if (t + 6 < nlog) q2 = __ldg(lgp + (ptrdiff_t)SGN * (t + 6) * 32);
        crf_step(g, Ea, Eb, rd0, wr1, lane, c, kf);
        g = q3; if (t + 7 < nlog) q3 = __ldg(lgp + (ptrdiff_t)SGN * (t + 7) * 32);
        crf_step(g, Ea, Eb, rd1, wr0, lane, c, kf);
    }
    for (; t < nlog; ++t) {
        float2 g = __ldg(lgp + (ptrdiff_t)SGN * t * 32);
        if (t & 1) crf_step(g, Ea, Eb, rd1, wr0, lane, c, kf);
        else       crf_step(g, Ea, Eb, rd0, wr1, lane, c, kf);
    }
    if (bare) {
        float2 g = make_float2(0.0f, 0.0f);
        if (t & 1) crf_step(g, Ea, Eb, rd1, wr0, lane, c, kf);
        else       crf_step(g, Ea, Eb, rd0, wr1, lane, c, kf);
    }
    return c;
}

__global__ void __launch_bounds__(64)
crf_fwd_kernel(const float* __restrict__ logits,
               const int*   __restrict__ lens,
               const float* __restrict__ trans,
               float*       __restrict__ out)
{
    __shared__ __align__(16) float2 sp[2][2][32];   // [warp][buffer][pair]
    __shared__ float2 fin[2][32];
    __shared__ float  cW[2];

    const int w    = threadIdx.x >> 5;              // 0 = fwd, 1 = bwd
    const int lane = threadIdx.x & 31;
    const int b    = blockIdx.x;                    // grid = 512

    const float2* rd0 = sp[w][0];
    const float2* rd1 = sp[w][1];
    u64* wr0 = reinterpret_cast<u64*>(sp[w][0]);
    u64* wr1 = reinterpret_cast<u64*>(sp[w][1]);

    const int len = lens[b];
    const int m   = len >> 1;                       // fwd steps; bwd = len-m

    // ---- E in registers: fwd = rows of exp(trans); bwd = rows of exp(trans)^T
    u64 Ea[32], Eb[32];
    if (w == 0) {
        const float* ra = trans + (2 * lane)     * CRF_L;
        const float* rb = trans + (2 * lane + 1) * CRF_L;
#pragma unroll
        for (int jj = 0; jj < 32; jj++) {
            Ea[jj] = packf2(expf(ra[2 * jj]), expf(ra[2 * jj + 1]));
            Eb[jj] = packf2(expf(rb[2 * jj]), expf(rb[2 * jj + 1]));
        }
    } else {
        const float* ca = trans + (2 * lane);       // column 2*lane
        const float* cb = trans + (2 * lane + 1);   // column 2*lane+1
#pragma unroll
        for (int jj = 0; jj < 32; jj++) {
            Ea[jj] = packf2(expf(ca[(2 * jj) * CRF_L]), expf(ca[(2 * jj + 1) * CRF_L]));
            Eb[jj] = packf2(expf(cb[(2 * jj) * CRF_L]), expf(cb[(2 * jj + 1) * CRF_L]));
        }
    }

    const float2* base =
        reinterpret_cast<const float2*>(logits + (size_t)b * CRF_T * CRF_L) + lane;

    float c;
    int   nsteps;

    if (w == 0) {
        // ---- forward: init = delta at start label 62, m logit steps ----
        wr0[lane] = packf2((2 * lane == 62) ? 1.0f : 0.0f,
                           (2 * lane + 1 == 62) ? 1.0f : 0.0f);
        __syncwarp();
        c = run_chain<+1>(base, m, false, Ea, Eb, rd0, rd1, wr0, wr1, lane);
        nsteps = m;
    } else {
        // ---- backward: init v = el_{len-1} .* e63 (or e63 if len==0) ----
        float e63x = expf(trans[63 * CRF_L + 2 * lane]);
        float e63y = expf(trans[63 * CRF_L + 2 * lane + 1]);
        if (len >= 1) {
            float2 lgl = __ldg(base + (ptrdiff_t)(len - 1) * 32);
            e63x *= expf(lgl.x);
            e63y *= expf(lgl.y);
        }
        wr0[lane] = packf2(e63x, e63y);
        __syncwarp();
        const int nlog = (len >= 1) ? (len - m - 1) : 0;
        const float2* lgb = base + (ptrdiff_t)(len - 2) * 32;
        c = run_chain<-1>(lgb, nlog, len >= 1, Ea, Eb, rd0, rd1, wr0, wr1, lane);
        nsteps = (len >= 1) ? (nlog + 1) : 0;
    }

    // ---- combine: logZ = cF + cB + log( sum_j pF[j] * pB[j] ) ----
    float px, py;
    unpackf2((nsteps & 1) ? wr1[lane] : wr0[lane], px, py);
    fin[w][lane] = make_float2(px, py);
    if (lane == 0) cW[w] = c;
    __syncthreads();

    if (w == 0) {
        float2 f = fin[0][lane];
        float2 g = fin[1][lane];
        float dot = f.x * g.x + f.y * g.y;
#pragma unroll
        for (int o = 16; o > 0; o >>= 1)
            dot += __shfl_xor_sync(FULLM, dot, o);
        if (lane == 0)
            out[b] = cW[0] + cW[1] + __logf(dot);
    }
}

extern "C" void kernel_launch(void* const* d_in, const int* in_sizes, int n_in,
                              void* d_out, int out_size)
{
    const float* logits = (const float*)d_in[0];   // [512,1024,64] f32
    const int*   lens   = (const int*)  d_in[1];   // [512] i32
    const float* trans  = (const float*)d_in[2];   // [64,64] f32
    float* out = (float*)d_out;                    // [512] f32

    crf_fwd_kernel<<<CRF_B, 64>>>(logits, lens, trans, out);
}

// round 10
// speedup vs baseline: 3.3451x; 1.4786x over previous
#include <cuda_runtime.h>
#include <cstdint>
#include <cstddef>

// CRF forward log-partition. B=512, T=1024, L=64.
// Fwd/bwd split (halves the serial chain): Z = e63^T M_{len-1}..M_0 delta,
// M_t = diag(el_t) E.
//   warp 0 (fwd): p = M_{m-1}..M_0 delta_start          (m = len/2 steps)
//   warp 1 (bwd): v = M_m^T..M_{len-1}^T e63            (len-m steps)
//                 via v' = el .* (E^T v), E^T in registers, logits reversed.
//   logZ = cF + cB + log( sum_j p[j] * v[j] )
// Inner step: front-batching FORCED in source -- 32 consecutive volatile
// ld.shared.b64 into an unrolled register array BEFORE any FMA (this is the
// schedule ptxas produced voluntarily only in Round 1; regs ~255 regime).
// Per-step exact power-of-2 rescale via REDUX on float bits (R1 semantics).

#define CRF_B 512
#define CRF_T 1024
#define CRF_L 64
#define C_LOG2E 1.4426950408889634f
#define C_LN2   0.6931471805599453f
#define FULLM  0xffffffffu

using u64 = unsigned long long;

__device__ __forceinline__ float ex2f(float x) {
    float r; asm("ex2.approx.f32 %0, %1;" : "=f"(r) : "f"(x)); return r;
}
__device__ __forceinline__ u64 packf2(float lo, float hi) {
    u64 r; asm("mov.b64 %0, {%1, %2};" : "=l"(r) : "f"(lo), "f"(hi)); return r;
}
__device__ __forceinline__ void unpackf2(u64 v, float& lo, float& hi) {
    asm("mov.b64 {%0, %1}, %2;" : "=f"(lo), "=f"(hi) : "l"(v));
}
__device__ __forceinline__ uint32_t smem_u32(const void* p) {
    uint32_t a;
    asm("{ .reg .u64 t; cvta.to.shared.u64 t, %1; cvt.u32.u64 %0, t; }"
        : "=r"(a) : "l"(p));
    return a;
}
#define FMA2(acc, a, b) \
    asm("fma.rn.f32x2 %0, %1, %2, %0;" : "+l"(acc) : "l"(a), "l"(b))
#define ADD2(acc, a) \
    asm("add.rn.f32x2 %0, %0, %1;" : "+l"(acc) : "l"(a))

// One CRF step, R1 semantics, with source-forced load front-batching.
__device__ __forceinline__ void crf_step(
    float2 lg,
    const u64 (&Ea)[32], const u64 (&Eb)[32],
    uint32_t rda, uint32_t wra,
    int lane, float& c, float& kf)
{
    // ---- 32 back-to-back LDS.64 broadcasts (volatile: order pinned) ----
    u64 p[32];
#pragma unroll
    for (int i = 0; i < 32; i++)
        asm volatile("ld.shared.b64 %0, [%1];"
                     : "=l"(p[i]) : "r"(rda + 8u * i));

    u64 a0 = 0ull, a1 = 0ull, b0 = 0ull, b1 = 0ull;
#pragma unroll
    for (int jj = 0; jj < 32; jj += 2) {
        FMA2(a0, Ea[jj],     p[jj]);
        FMA2(b0, Eb[jj],     p[jj]);
        FMA2(a1, Ea[jj + 1], p[jj + 1]);
        FMA2(b1, Eb[jj + 1], p[jj + 1]);
    }
    ADD2(a0, a1);
    ADD2(b0, b1);
    float ax, ay, bx, by;
    unpackf2(a0, ax, ay);
    unpackf2(b0, bx, by);
    float sA = ax + ay;
    float sB = bx + by;

    float elA = ex2f(fmaf(lg.x, C_LOG2E, -kf));
    float elB = ex2f(fmaf(lg.y, C_LOG2E, -kf));
    float pA = sA * elA;
    float pB = sB * elB;

    asm volatile("st.shared.b64 [%0], %1;"
                 :: "r"(wra + 8u * (uint32_t)lane), "l"(packf2(pA, pB)));

    c = fmaf(kf, C_LN2, c);
    float m = fmaxf(pA, pB);                 // p > 0: uint cmp == float cmp
    unsigned mu = __reduce_max_sync(FULLM, __float_as_uint(m));
    kf = (float)((int)(mu >> 23) - 127);

    __syncwarp();
}

// Main loop (R1/R9 shape), stride sign compile-time. Runs nlog logit steps,
// then optional bare step (lg = 0 -> el = 2^-kf).
template <int SGN>
__device__ __forceinline__ float run_chain(
    const float2* __restrict__ lgp, int nlog, bool bare,
    const u64 (&Ea)[32], const u64 (&Eb)[32],
    uint32_t b0a, uint32_t b1a, int lane)
{
    float c = 0.0f, kf = 0.0f;

    float2 q0, q1, q2, q3;
    if (nlog > 0) q0 = __ldg(lgp);
    if (nlog > 1) q1 = __ldg(lgp + SGN * 32);
    if (nlog > 2) q2 = __ldg(lgp + SGN * 64);
    if (nlog > 3) q3 = __ldg(lgp + SGN * 96);

    int t = 0;
    for (; t + 4 <= nlog; t += 4) {
        float2 g;
        g = q0; if (t + 4 < nlog) q0 = __ldg(lgp + (ptrdiff_t)SGN * (t + 4) * 32);
        crf_step(g, Ea, Eb, b0a, b1a, lane, c, kf);
        g = q1; if (t + 5 < nlog) q1 = __ldg(lgp + (ptrdiff_t)SGN * (t + 5) * 32);
        crf_step(g, Ea, Eb, b1a, b0a, lane, c, kf);
        g = q2; if (t + 6 < nlog) q2 = __ldg(lgp + (ptrdiff_t)SGN * (t + 6) * 32);
        crf_step(g, Ea, Eb, b0a, b1a, lane, c, kf);
        g = q3; if (t + 7 < nlog) q3 = __ldg(lgp + (ptrdiff_t)SGN * (t + 7) * 32);
        crf_step(g, Ea, Eb, b1a, b0a, lane, c, kf);
    }
    for (; t < nlog; ++t) {
        float2 g = __ldg(lgp + (ptrdiff_t)SGN * t * 32);
        if (t & 1) crf_step(g, Ea, Eb, b1a, b0a, lane, c, kf);
        else       crf_step(g, Ea, Eb, b0a, b1a, lane, c, kf);
    }
    if (bare) {
        float2 g = make_float2(0.0f, 0.0f);
        if (t & 1) crf_step(g, Ea, Eb, b1a, b0a, lane, c, kf);
        else       crf_step(g, Ea, Eb, b0a, b1a, lane, c, kf);
    }
    return c;
}

__global__ void __launch_bounds__(64)
crf_fwd_kernel(const float* __restrict__ logits,
               const int*   __restrict__ lens,
               const float* __restrict__ trans,
               float*       __restrict__ out)
{
    __shared__ __align__(16) float2 sp[2][2][32];   // [warp][buffer][pair]
    __shared__ float2 fin[2][32];
    __shared__ float  cW[2];

    const int w    = threadIdx.x >> 5;              // 0 = fwd, 1 = bwd
    const int lane = threadIdx.x & 31;
    const int b    = blockIdx.x;                    // grid = 512

    const uint32_t b0a = smem_u32(sp[w][0]);
    const uint32_t b1a = smem_u32(sp[w][1]);
    u64* wr0 = reinterpret_cast<u64*>(sp[w][0]);
    u64* wr1 = reinterpret_cast<u64*>(sp[w][1]);

    const int len = lens[b];
    const int m   = len >> 1;                       // fwd steps; bwd = len-m

    // ---- E in registers: fwd = rows of exp(trans); bwd = columns ----
    u64 Ea[32], Eb[32];
    if (w == 0) {
        const float* ra = trans + (2 * lane)     * CRF_L;
        const float* rb = trans + (2 * lane + 1) * CRF_L;
#pragma unroll
        for (int jj = 0; jj < 32; jj++) {
            Ea[jj] = packf2(expf(ra[2 * jj]), expf(ra[2 * jj + 1]));
            Eb[jj] = packf2(expf(rb[2 * jj]), expf(rb[2 * jj + 1]));
        }
    } else {
        const float* ca = trans + (2 * lane);       // column 2*lane
        const float* cb = trans + (2 * lane + 1);   // column 2*lane+1
#pragma unroll
        for (int jj = 0; jj < 32; jj++) {
            Ea[jj] = packf2(expf(ca[(2 * jj) * CRF_L]), expf(ca[(2 * jj + 1) * CRF_L]));
            Eb[jj] = packf2(expf(cb[(2 * jj) * CRF_L]), expf(cb[(2 * jj + 1) * CRF_L]));
        }
    }

    const float2* base =
        reinterpret_cast<const float2*>(logits + (size_t)b * CRF_T * CRF_L) + lane;

    float c;
    int   nsteps;

    if (w == 0) {
        // ---- forward: init = delta at start label 62, m logit steps ----
        wr0[lane] = packf2((2 * lane == 62) ? 1.0f : 0.0f,
                           (2 * lane + 1 == 62) ? 1.0f : 0.0f);
        __syncwarp();
        c = run_chain<+1>(base, m, false, Ea, Eb, b0a, b1a, lane);
        nsteps = m;
    } else {
        // ---- backward: init v = el_{len-1} .* e63 (or e63 if len==0) ----
        float e63x = expf(trans[63 * CRF_L + 2 * lane]);
        float e63y = expf(trans[63 * CRF_L + 2 * lane + 1]);
        if (len >= 1) {
            float2 lgl = __ldg(base + (ptrdiff_t)(len - 1) * 32);
            e63x *= expf(lgl.x);
            e63y *= expf(lgl.y);
        }
        wr0[lane] = packf2(e63x, e63y);
        __syncwarp();
        const int nlog = (len >= 1) ? (len - m - 1) : 0;
        const float2* lgb = base + (ptrdiff_t)(len - 2) * 32;
        c = run_chain<-1>(lgb, nlog, len >= 1, Ea, Eb, b0a, b1a, lane);
        nsteps = (len >= 1) ? (nlog + 1) : 0;
    }

    // ---- combine: logZ = cF + cB + log( sum_j pF[j] * pB[j] ) ----
    float px, py;
    unpackf2((nsteps & 1) ? wr1[lane] : wr0[lane], px, py);
    fin[w][lane] = make_float2(px, py);
    if (lane == 0) cW[w] = c;
    __syncthreads();

    if (w == 0) {
        float2 f = fin[0][lane];
        float2 g = fin[1][lane];
        float dot = f.x * g.x + f.y * g.y;
#pragma unroll
        for (int o = 16; o > 0; o >>= 1)
            dot += __shfl_xor_sync(FULLM, dot, o);
        if (lane == 0)
            out[b] = cW[0] + cW[1] + __logf(dot);
    }
}

extern "C" void kernel_launch(void* const* d_in, const int* in_sizes, int n_in,
                              void* d_out, int out_size)
{
    const float* logits = (const float*)d_in[0];   // [512,1024,64] f32
    const int*   lens   = (const int*)  d_in[1];   // [512] i32
    const float* trans  = (const float*)d_in[2];   // [64,64] f32
    float* out = (float*)d_out;                    // [512] f32

    crf_fwd_kernel<<<CRF_B, 64>>>(logits, lens, trans, out);
}

// round 11
// speedup vs baseline: 3.4228x; 1.0232x over previous
#include <cuda_runtime.h>
#include <cstdint>
#include <cstddef>

// CRF forward log-partition. B=512, T=1024, L=64.
// Fwd/bwd split (halves the serial chain): Z = e63^T M_{len-1}..M_0 delta,
// M_t = diag(el_t) E.
//   warp 0 (fwd): p = M_{m-1}..M_0 delta_start          (m = len/2 steps)
//   warp 1 (bwd): v = M_m^T..M_{len-1}^T e63            (len-m steps)
// logZ = (ktF+ktB)*ln2 + log( sum_j p[j] * v[j] )
//
// Step core is source-forced (volatile asm): 16x ld.shared.v2.b64 front-batch,
// 8 named f32x2 accumulators (dep depth 8), st.shared.b64.
// Rescale every 4 steps, fully deferred: group = FOLD,plain,plain,RECORD.
// RECORD issues REDUX.MAX -> mu after the store (no consumer that step);
// the next group's FOLD converts mu -> exact 2^-k and folds into exp(logit),
// which now depends only on the prefetched logit -> computed at step top.

#define CRF_B 512
#define CRF_T 1024
#define CRF_L 64
#define C_LOG2E 1.4426950408889634f
#define C_LN2   0.6931471805599453f
#define FULLM  0xffffffffu

using u64 = unsigned long long;

__device__ __forceinline__ float ex2f(float x) {
    float r; asm("ex2.approx.f32 %0, %1;" : "=f"(r) : "f"(x)); return r;
}
__device__ __forceinline__ u64 packf2(float lo, float hi) {
    u64 r; asm("mov.b64 %0, {%1, %2};" : "=l"(r) : "f"(lo), "f"(hi)); return r;
}
__device__ __forceinline__ void unpackf2(u64 v, float& lo, float& hi) {
    asm("mov.b64 {%0, %1}, %2;" : "=f"(lo), "=f"(hi) : "l"(v));
}
__device__ __forceinline__ uint32_t smem_u32(const void* p) {
    uint32_t a;
    asm("{ .reg .u64 t; cvta.to.shared.u64 t, %1; cvt.u32.u64 %0, t; }"
        : "=r"(a) : "l"(p));
    return a;
}
#define FMA2(acc, a, b) \
    asm("fma.rn.f32x2 %0, %1, %2, %0;" : "+l"(acc) : "l"(a), "l"(b))
#define ADD2(acc, a) \
    asm("add.rn.f32x2 %0, %0, %1;" : "+l"(acc) : "l"(a))
#define LDSV2(lo, hi, addr) \
    asm volatile("ld.shared.v2.b64 {%0, %1}, [%2];" \
                 : "=l"(lo), "=l"(hi) : "r"(addr))

// One CRF step. FOLD: consume mu (recorded last group; ~3 steps old -> ready),
// fold exact 2^-k into el. REC: record REDUX.MAX of new p into mu (no
// consumer this step).
template <bool FOLD, bool REC>
__device__ __forceinline__ void crf_step(
    float2 lg,
    const u64 (&Ea)[32], const u64 (&Eb)[32],
    uint32_t rda, uint32_t wra,
    int lane, int& ktot, unsigned& mu)
{
    // el at step top: depends only on prefetched logit (+ stale mu if FOLD).
    float elA = ex2f(lg.x * C_LOG2E);
    float elB = ex2f(lg.y * C_LOG2E);
    if (FOLD) {
        int k = (int)(mu >> 23) - 127;
        ktot += k;
        float s = __int_as_float((127 - k) << 23);   // exact 2^-k
        elA *= s;
        elB *= s;
    }

    // ---- 16 back-to-back LDS.128 broadcasts (volatile: order pinned) ----
    u64 p[32];
#pragma unroll
    for (int i = 0; i < 16; i++)
        LDSV2(p[2 * i], p[2 * i + 1], rda + 16u * i);

    u64 a0 = 0ull, a1 = 0ull, a2 = 0ull, a3 = 0ull;
    u64 b0 = 0ull, b1 = 0ull, b2 = 0ull, b3 = 0ull;
#pragma unroll
    for (int jj = 0; jj < 32; jj += 4) {
        FMA2(a0, Ea[jj],     p[jj]);
        FMA2(b0, Eb[jj],     p[jj]);
        FMA2(a1, Ea[jj + 1], p[jj + 1]);
        FMA2(b1, Eb[jj + 1], p[jj + 1]);
        FMA2(a2, Ea[jj + 2], p[jj + 2]);
        FMA2(b2, Eb[jj + 2], p[jj + 2]);
        FMA2(a3, Ea[jj + 3], p[jj + 3]);
        FMA2(b3, Eb[jj + 3], p[jj + 3]);
    }
    ADD2(a0, a1); ADD2(a2, a3); ADD2(a0, a2);
    ADD2(b0, b1); ADD2(b2, b3); ADD2(b0, b2);
    float ax, ay, bx, by;
    unpackf2(a0, ax, ay);
    unpackf2(b0, bx, by);
    float pA = (ax + ay) * elA;            // new p[2*lane]
    float pB = (bx + by) * elB;            // new p[2*lane+1]

    asm volatile("st.shared.b64 [%0], %1;"
                 :: "r"(wra + 8u * (uint32_t)lane), "l"(packf2(pA, pB)));

    if (REC) {                             // no consumer this step
        mu = __reduce_max_sync(FULLM, __float_as_uint(fmaxf(pA, pB)));
    }
    __syncwarp();
}

// Runs nlog logit steps (stride SGN*32 float2 per t) then optional bare step
// (lg = 0 -> el = 1). Groups of 4: FOLD,plain,plain,RECORD.
template <int SGN>
__device__ __forceinline__ int run_chain(
    const float2* __restrict__ lgp, int nlog, bool bare,
    const u64 (&Ea)[32], const u64 (&Eb)[32],
    uint32_t b0a, uint32_t b1a, int lane)
{
    int      ktot = 0;
    unsigned mu   = 0x3f800000u;           // 1.0f bits -> first fold k=0

    float2 q0, q1, q2, q3;
    if (nlog > 0) q0 = __ldg(lgp);
    if (nlog > 1) q1 = __ldg(lgp + SGN * 32);
    if (nlog > 2) q2 = __ldg(lgp + SGN * 64);
    if (nlog > 3) q3 = __ldg(lgp + SGN * 96);

    int t = 0;
    for (; t + 4 <= nlog; t += 4) {
        float2 g;
        g = q0; if (t + 4 < nlog) q0 = __ldg(lgp + (ptrdiff_t)SGN * (t + 4) * 32);
        crf_step<true,  false>(g, Ea, Eb, b0a, b1a, lane, ktot, mu);
        g = q1; if (t + 5 < nlog) q1 = __ldg(lgp + (ptrdiff_t)SGN * (t + 5) * 32);
        crf_step<false, false>(g, Ea, Eb, b1a, b0a, lane, ktot, mu);
        g = q2; if (t + 6 < nlog) q2 = __ldg(lgp + (ptrdiff_t)SGN * (t + 6) * 32);
        crf_step<false, false>(g, Ea, Eb, b0a, b1a, lane, ktot, mu);
        g = q3; if (t + 7 < nlog) q3 = __ldg(lgp + (ptrdiff_t)SGN * (t + 7) * 32);
        crf_step<false, true >(g, Ea, Eb, b1a, b0a, lane, ktot, mu);
    }

    // Remainder (<=3 steps, t%4==0 entering): fold pending mu on the first.
    bool pend = (t > 0);
    if (t < nlog) {
        if (pend) crf_step<true,  false>(q0, Ea, Eb, b0a, b1a, lane, ktot, mu);
        else      crf_step<false, false>(q0, Ea, Eb, b0a, b1a, lane, ktot, mu);
        pend = false; t++;
    }
    if (t < nlog) { crf_step<false, false>(q1, Ea, Eb, b1a, b0a, lane, ktot, mu); t++; }
    if (t < nlog) { crf_step<false, false>(q2, Ea, Eb, b0a, b1a, lane, ktot, mu); t++; }

    if (bare) {
        float2 g = make_float2(0.0f, 0.0f);
        bool odd = (t & 1);
        if (pend) {
            if (odd) crf_step<true, false>(g, Ea, Eb, b1a, b0a, lane, ktot, mu);
            else     crf_step<true, false>(g, Ea, Eb, b0a, b1a, lane, ktot, mu);
        } else {
            if (odd) crf_step<false, false>(g, Ea, Eb, b1a, b0a, lane, ktot, mu);
            else     crf_step<false, false>(g, Ea, Eb, b0a, b1a, lane, ktot, mu);
        }
    }
    return ktot;
}

__global__ void __launch_bounds__(64)
crf_fwd_kernel(const float* __restrict__ logits,
               const int*   __restrict__ lens,
               const float* __restrict__ trans,
               float*       __restrict__ out)
{
    __shared__ __align__(16) float2 sp[2][2][32];   // [warp][buffer][pair]
    __shared__ float2 fin[2][32];
    __shared__ int    ktW[2];

    const int w    = threadIdx.x >> 5;              // 0 = fwd, 1 = bwd
    const int lane = threadIdx.x & 31;
    const int b    = blockIdx.x;                    // grid = 512

    const uint32_t b0a = smem_u32(sp[w][0]);
    const uint32_t b1a = smem_u32(sp[w][1]);
    u64* wr0 = reinterpret_cast<u64*>(sp[w][0]);
    u64* wr1 = reinterpret_cast<u64*>(sp[w][1]);

    const int len = lens[b];
    const int m   = len >> 1;                       // fwd steps; bwd = len-m

    // ---- E in registers: fwd = rows of exp(trans); bwd = columns ----
    u64 Ea[32], Eb[32];
    if (w == 0) {
        const float* ra = trans + (2 * lane)     * CRF_L;
        const float* rb = trans + (2 * lane + 1) * CRF_L;
#pragma unroll
        for (int jj = 0; jj < 32; jj++) {
            Ea[jj] = packf2(expf(ra[2 * jj]), expf(ra[2 * jj + 1]));
            Eb[jj] = packf2(expf(rb[2 * jj]), expf(rb[2 * jj + 1]));
        }
    } else {
        const float* ca = trans + (2 * lane);       // column 2*lane
        const float* cb = trans + (2 * lane + 1);   // column 2*lane+1
#pragma unroll
        for (int jj = 0; jj < 32; jj++) {
            Ea[jj] = packf2(expf(ca[(2 * jj) * CRF_L]), expf(ca[(2 * jj + 1) * CRF_L]));
            Eb[jj] = packf2(expf(cb[(2 * jj) * CRF_L]), expf(cb[(2 * jj + 1) * CRF_L]));
        }
    }

    const float2* base =
        reinterpret_cast<const float2*>(logits + (size_t)b * CRF_T * CRF_L) + lane;

    int kt;
    int nsteps;

    if (w == 0) {
        // ---- forward: init = delta at start label 62, m logit steps ----
        wr0[lane] = packf2((2 * lane == 62) ? 1.0f : 0.0f,
                           (2 * lane + 1 == 62) ? 1.0f : 0.0f);
        __syncwarp();
        kt = run_chain<+1>(base, m, false, Ea, Eb, b0a, b1a, lane);
        nsteps = m;
    } else {
        // ---- backward: init v = el_{len-1} .* e63 (or e63 if len==0) ----
        float e63x = expf(trans[63 * CRF_L + 2 * lane]);
        float e63y = expf(trans[63 * CRF_L + 2 * lane + 1]);
        if (len >= 1) {
            float2 lgl = __ldg(base + (ptrdiff_t)(len - 1) * 32);
            e63x *= expf(lgl.x);
            e63y *= expf(lgl.y);
        }
        wr0[lane] = packf2(e63x, e63y);
        __syncwarp();
        const int nlog = (len >= 1) ? (len - m - 1) : 0;
        const float2* lgb = base + (ptrdiff_t)(len - 2) * 32;
        kt = run_chain<-1>(lgb, nlog, len >= 1, Ea, Eb, b0a, b1a, lane);
        nsteps = (len >= 1) ? (nlog + 1) : 0;
    }

    // ---- combine: logZ = (ktF+ktB)*ln2 + log( sum_j pF[j] * pB[j] ) ----
    float px, py;
    unpackf2((nsteps & 1) ? wr1[lane] : wr0[lane], px, py);
    fin[w][lane] = make_float2(px, py);
    if (lane == 0) ktW[w] = kt;
    __syncthreads();

    if (w == 0) {
        float2 f = fin[0][lane];
        float2 g = fin[1][lane];
        float dot = f.x * g.x + f.y * g.y;
#pragma unroll
        for (int o = 16; o > 0; o >>= 1)
            dot += __shfl_xor_sync(FULLM, dot, o);
        if (lane == 0)
            out[b] = (float)(ktW[0] + ktW[1]) * C_LN2 + __logf(dot);
    }
}

extern "C" void kernel_launch(void* const* d_in, const int* in_sizes, int n_in,
                              void* d_out, int out_size)
{
    const float* logits = (const float*)d_in[0];   // [512,1024,64] f32
    const int*   lens   = (const int*)  d_in[1];   // [512] i32
    const float* trans  = (const float*)d_in[2];   // [64,64] f32
    float* out = (float*)d_out;                    // [512] f32

    crf_fwd_kernel<<<CRF_B, 64>>>(logits, lens, trans, out);
}